// round 16
// baseline (speedup 1.0000x reference)
#include <cuda_runtime.h>
#include <cuda_bf16.h>
#include <cstdint>

#define NODES_MAX 100000
#define DIM 128

typedef unsigned int u32;

// Scratch (allocation-free rule: __device__ globals; zero-init at load)
__device__ float g_h[(size_t)NODES_MAX * DIM];     // relu(x@W0^T+b0)
__device__ float g_agg[(size_t)NODES_MAX * DIM];   // scatter-add accumulator (kept zeroed by gemm1)
__device__ float g_deg[NODES_MAX];                 // degree accumulator (kept zeroed by gemm1)
__device__ uint4 g_w0s[4096];                      // W0 split-bf16, swizzled tile layout (hi 2048, lo 2048)
__device__ uint4 g_w1s[4096];                      // W1 split-bf16, swizzled tile layout

// ---------------- smem layout (bytes) ----------------
#define OFF_BIAS 0            // 128 f32
#define OFF_WC   512          // 512 f32
#define OFF_BC   2560         // 4 f32
#define OFF_INVD 2576         // 64 f32
#define OFF_CP   4096         // 4KB classifier cross-warp partials
#define OFF_AH   8192         // 16KB (64x128 bf16)
#define OFF_AL   24576        // 16KB
#define OFF_BH   40960        // 32KB (128x128 bf16)
#define OFF_BL   73728        // 32KB (must be OFF_BH + 32768 for linear B copy)
#define SMEM_BYTES 106496

// ---------------- helpers ----------------
__device__ __forceinline__ u32 smem_u32(const void* p) {
    u32 a;
    asm("{ .reg .u64 t; cvta.to.shared.u64 t, %1; cvt.u32.u64 %0, t; }" : "=r"(a) : "l"(p));
    return a;
}

__device__ __forceinline__ void cp_async16(u32 smem, const void* gptr) {
    asm volatile("cp.async.cg.shared.global [%0], [%1], 16;" :: "r"(smem), "l"(gptr));
}

__device__ __forceinline__ void ldsm_x4(u32* r, u32 addr) {
    asm volatile("ldmatrix.sync.aligned.m8n8.x4.shared.b16 {%0,%1,%2,%3}, [%4];"
                 : "=r"(r[0]), "=r"(r[1]), "=r"(r[2]), "=r"(r[3]) : "r"(addr));
}

__device__ __forceinline__ void mma_bf16(float* d, const u32* a, u32 b0, u32 b1) {
    asm volatile(
        "mma.sync.aligned.m16n8k16.row.col.f32.bf16.bf16.f32 "
        "{%0,%1,%2,%3}, {%4,%5,%6,%7}, {%8,%9}, {%0,%1,%2,%3};"
        : "+f"(d[0]), "+f"(d[1]), "+f"(d[2]), "+f"(d[3])
        : "r"(a[0]), "r"(a[1]), "r"(a[2]), "r"(a[3]), "r"(b0), "r"(b1));
}

// byte offset of 16B chunk (row, c8) in a 256B-pitch tile, XOR-8 swizzle
__device__ __forceinline__ u32 tile_off(int row, int c8) {
    return (u32)(row * 256 + (((c8 >> 3) ^ (row & 7)) << 4));
}

// hi/lo bf16 split of 8 floats -> two 16B chunks
__device__ __forceinline__ void split8(const float* v, uint4& hi, uint4& lo) {
    u32 h[4], l[4];
#pragma unroll
    for (int j = 0; j < 4; j++) {
        float2 f = make_float2(v[2*j], v[2*j+1]);
        __nv_bfloat162 hb = __float22bfloat162_rn(f);
        float2 hf = __bfloat1622float2(hb);
        float2 r = make_float2(f.x - hf.x, f.y - hf.y);
        __nv_bfloat162 lb = __float22bfloat162_rn(r);
        h[j] = *(u32*)&hb;
        l[j] = *(u32*)&lb;
    }
    hi = make_uint4(h[0], h[1], h[2], h[3]);
    lo = make_uint4(l[0], l[1], l[2], l[3]);
}

__device__ __forceinline__ void split_store(char* smb, int hi_off, int lo_off,
                                            u32 sw, const float* v) {
    uint4 hi, lo;
    split8(v, hi, lo);
    *(uint4*)(smb + hi_off + sw) = hi;
    *(uint4*)(smb + lo_off + sw) = lo;
}

// ---------------------------------------------------------------------------
// Prep: split W0/W1 into bf16 hi/lo, stored in the EXACT swizzled tile layout
// so GEMM CTAs stage B with a pure linear 16B-chunk copy. blockIdx.x: 0=W0,1=W1
// ---------------------------------------------------------------------------
__global__ __launch_bounds__(256) void prep_w(const float* __restrict__ W0,
                                              const float* __restrict__ W1)
{
    const float* W = blockIdx.x ? W1 : W0;
    uint4* dst     = blockIdx.x ? g_w1s : g_w0s;
    const int tid = threadIdx.x;
#pragma unroll
    for (int s = 0; s < 8; s++) {
        const int chunk = tid + s * 256;          // 0..2047
        const int row = chunk >> 4, c8 = (chunk & 15) << 3;
        float w[8];
        float4 w0 = *(const float4*)(W + row * DIM + c8);
        float4 w1 = *(const float4*)(W + row * DIM + c8 + 4);
        w[0]=w0.x; w[1]=w0.y; w[2]=w0.z; w[3]=w0.w;
        w[4]=w1.x; w[5]=w1.y; w[6]=w1.z; w[7]=w1.w;
        uint4 hi, lo;
        split8(w, hi, lo);
        const u32 off = tile_off(row, c8) >> 4;
        dst[off]        = hi;
        dst[2048 + off] = lo;
    }
}

// stage B: pure async copy of the prepped 64KB (hi 32KB @ OFF_BH, lo follows)
__device__ __forceinline__ void stage_B_copy(u32 sb, const uint4* __restrict__ src, int tid) {
#pragma unroll
    for (int s = 0; s < 16; s++) {
        const int i = tid + s * 256;              // 0..4095
        cp_async16(sb + OFF_BH + i * 16, src + i);
    }
    asm volatile("cp.async.commit_group;" ::: "memory");
}

// mainloop: warp tile 32m x 32n. mt = m-half (0..1), ng = n-quarter (0..3).
__device__ __forceinline__ void mainloop_32x32(float acc[2][4][4], u32 sb,
                                               int mt, int ng, int lane) {
    const int l7     = lane & 7;
    const int a_sel  = lane >> 4;
    const int b_rowl = l7 + ((lane >> 4) << 3);
    const int b_sel  = (lane >> 3) & 1;
    const int arow0  = mt * 32 + (lane & 15);

    u32 aH[2][4], aL[2][4], bH[2][4], bL[2][4];
#pragma unroll
    for (int kk = 0; kk < 8; kk++) {
        const u32 ao = (u32)(((2 * kk + a_sel) ^ l7) << 4);
        const u32 bo = (u32)(((2 * kk + b_sel) ^ l7) << 4);
#pragma unroll
        for (int at = 0; at < 2; at++) {
            const u32 ar = (u32)((arow0 + at * 16) * 256);
            ldsm_x4(aH[at], sb + OFF_AH + ar + ao);
            ldsm_x4(aL[at], sb + OFF_AL + ar + ao);
        }
#pragma unroll
        for (int g = 0; g < 2; g++) {
            const u32 br = (u32)((ng * 32 + g * 16 + b_rowl) * 256);
            ldsm_x4(bH[g], sb + OFF_BH + br + bo);
            ldsm_x4(bL[g], sb + OFF_BL + br + bo);
        }
#pragma unroll
        for (int at = 0; at < 2; at++)
#pragma unroll
            for (int g = 0; g < 2; g++) {
                mma_bf16(acc[at][2*g],   aH[at], bH[g][0], bH[g][1]);
                mma_bf16(acc[at][2*g+1], aH[at], bH[g][2], bH[g][3]);
            }
#pragma unroll
        for (int at = 0; at < 2; at++)
#pragma unroll
            for (int g = 0; g < 2; g++) {
                mma_bf16(acc[at][2*g],   aH[at], bL[g][0], bL[g][1]);
                mma_bf16(acc[at][2*g+1], aH[at], bL[g][2], bL[g][3]);
            }
#pragma unroll
        for (int at = 0; at < 2; at++)
#pragma unroll
            for (int g = 0; g < 2; g++) {
                mma_bf16(acc[at][2*g],   aL[at], bH[g][0], bH[g][1]);
                mma_bf16(acc[at][2*g+1], aL[at], bH[g][2], bH[g][3]);
            }
    }
}

// ---------------------------------------------------------------------------
// GEMM0: h = relu(x @ W0^T + b0). CTA 64x128, 256 threads, warps 2m x 4n.
// ---------------------------------------------------------------------------
__global__ __launch_bounds__(256, 2) void gemm0_mma(
    const float* __restrict__ A,
    const float* __restrict__ bias, float* __restrict__ C, int n)
{
    extern __shared__ char sm[];
    const u32 sb = smem_u32(sm);
    const int tid = threadIdx.x, wid = tid >> 5, lane = tid & 31;
    const int R0 = blockIdx.x * 64;

    stage_B_copy(sb, g_w0s, tid);   // async B while we stage A

    if (tid < 128) ((float*)(sm + OFF_BIAS))[tid] = bias[tid];

    // stage A (64x128, split bf16)
#pragma unroll
    for (int s = 0; s < 4; s++) {
        const int chunk = tid + s * 256;
        const int row = chunk >> 4, c8 = (chunk & 15) << 3;
        const u32 sw = tile_off(row, c8);
        float v[8];
        const int gr = R0 + row;
        if (gr < n) {
            float4 a0 = *(const float4*)(A + (size_t)gr * DIM + c8);
            float4 a1 = *(const float4*)(A + (size_t)gr * DIM + c8 + 4);
            v[0]=a0.x; v[1]=a0.y; v[2]=a0.z; v[3]=a0.w;
            v[4]=a1.x; v[5]=a1.y; v[6]=a1.z; v[7]=a1.w;
        } else {
#pragma unroll
            for (int j = 0; j < 8; j++) v[j] = 0.f;
        }
        split_store(sm, OFF_AH, OFF_AL, sw, v);
    }
    asm volatile("cp.async.wait_group 0;" ::: "memory");
    __syncthreads();

    float acc[2][4][4];
#pragma unroll
    for (int at = 0; at < 2; at++)
#pragma unroll
        for (int j = 0; j < 4; j++)
#pragma unroll
            for (int q = 0; q < 4; q++) acc[at][j][q] = 0.f;

    const int mt = wid >> 2, ng = wid & 3;
    mainloop_32x32(acc, sb, mt, ng, lane);

    // epilogue: bias + relu -> C
    const float* bp = (const float*)(sm + OFF_BIAS);
#pragma unroll
    for (int at = 0; at < 2; at++) {
        const int r0 = R0 + mt * 32 + at * 16 + (lane >> 2), r1 = r0 + 8;
#pragma unroll
        for (int j = 0; j < 4; j++) {
            const int col = ng * 32 + (j >> 1) * 16 + (j & 1) * 8 + (lane & 3) * 2;
            const float2 bb = *(const float2*)(bp + col);
            if (r0 < n) {
                float2 o = make_float2(fmaxf(acc[at][j][0] + bb.x, 0.f),
                                       fmaxf(acc[at][j][1] + bb.y, 0.f));
                *(float2*)(C + (size_t)r0 * DIM + col) = o;
            }
            if (r1 < n) {
                float2 o = make_float2(fmaxf(acc[at][j][2] + bb.x, 0.f),
                                       fmaxf(acc[at][j][3] + bb.y, 0.f));
                *(float2*)(C + (size_t)r1 * DIM + col) = o;
            }
        }
    }
}

// ---------------------------------------------------------------------------
// Scatter: one warp per edge. agg[row] += h[col] (vectorized RED), deg[row]+=1
// ---------------------------------------------------------------------------
__global__ __launch_bounds__(256) void scatter_kernel(
    const int* __restrict__ ei, int n_edges)
{
    int e    = blockIdx.x * 8 + (threadIdx.x >> 5);
    int lane = threadIdx.x & 31;
    if (e >= n_edges) return;
    int r = ei[e];
    int c = ei[n_edges + e];

    const float4 v = *(const float4*)(g_h + (size_t)c * DIM + lane * 4);
    float* dst = g_agg + (size_t)r * DIM + lane * 4;
    asm volatile("red.global.add.v4.f32 [%0], {%1,%2,%3,%4};"
                 :: "l"(dst), "f"(v.x), "f"(v.y), "f"(v.z), "f"(v.w)
                 : "memory");
    if (lane == 0)
        asm volatile("red.global.add.f32 [%0], %1;"
                     :: "l"(g_deg + r), "f"(1.0f) : "memory");
}

// ---------------------------------------------------------------------------
// GEMM1 + classifier. Also re-zeroes the agg rows / deg entries it consumed
// (restores the zero invariant -> no memsets needed; globals are zero-init).
// ---------------------------------------------------------------------------
__global__ __launch_bounds__(256, 2) void gemm1_mma(
    const float* __restrict__ b1,
    const float* __restrict__ Wc, const float* __restrict__ bc,
    float* __restrict__ out, int n)
{
    extern __shared__ char sm[];
    const u32 sb = smem_u32(sm);
    const int tid = threadIdx.x, wid = tid >> 5, lane = tid & 31;
    const int R0 = blockIdx.x * 64;

    stage_B_copy(sb, g_w1s, tid);   // async B while we stage A

    if (tid < 128) ((float*)(sm + OFF_BIAS))[tid] = b1[tid];
    ((float*)(sm + OFF_WC))[tid]       = Wc[tid];
    ((float*)(sm + OFF_WC))[tid + 256] = Wc[tid + 256];
    if (tid < 4) ((float*)(sm + OFF_BC))[tid] = bc[tid];
    if (tid < 64) {
        const int r = R0 + tid;
        float d = 0.f;
        if (r < n) { d = g_deg[r]; g_deg[r] = 0.f; }   // consume + re-zero
        ((float*)(sm + OFF_INVD))[tid] = (r < n) ? (1.0f / fmaxf(d, 1.0f)) : 0.f;
    }
    __syncthreads();   // invd visible before A staging reads it
    const float* invd_s = (const float*)(sm + OFF_INVD);

    // stage A = h + agg*invd (64x128, split bf16); re-zero agg as we go
#pragma unroll
    for (int s = 0; s < 4; s++) {
        const int chunk = tid + s * 256;
        const int row = chunk >> 4, c8 = (chunk & 15) << 3;
        const u32 sw = tile_off(row, c8);
        float v[8];
        const int gr = R0 + row;
        if (gr < n) {
            const float id = invd_s[row];
            float4 h0 = *(const float4*)(g_h   + (size_t)gr * DIM + c8);
            float4 h1 = *(const float4*)(g_h   + (size_t)gr * DIM + c8 + 4);
            float4 g0 = *(const float4*)(g_agg + (size_t)gr * DIM + c8);
            float4 g1 = *(const float4*)(g_agg + (size_t)gr * DIM + c8 + 4);
            const float4 z = make_float4(0.f, 0.f, 0.f, 0.f);
            *(float4*)(g_agg + (size_t)gr * DIM + c8)     = z;   // L2-hot re-zero
            *(float4*)(g_agg + (size_t)gr * DIM + c8 + 4) = z;
            v[0]=fmaf(g0.x,id,h0.x); v[1]=fmaf(g0.y,id,h0.y);
            v[2]=fmaf(g0.z,id,h0.z); v[3]=fmaf(g0.w,id,h0.w);
            v[4]=fmaf(g1.x,id,h1.x); v[5]=fmaf(g1.y,id,h1.y);
            v[6]=fmaf(g1.z,id,h1.z); v[7]=fmaf(g1.w,id,h1.w);
        } else {
#pragma unroll
            for (int j = 0; j < 8; j++) v[j] = 0.f;
        }
        split_store(sm, OFF_AH, OFF_AL, sw, v);
    }
    asm volatile("cp.async.wait_group 0;" ::: "memory");
    __syncthreads();

    float acc[2][4][4];
#pragma unroll
    for (int at = 0; at < 2; at++)
#pragma unroll
        for (int j = 0; j < 4; j++)
#pragma unroll
            for (int q = 0; q < 4; q++) acc[at][j][q] = 0.f;

    const int mt = wid >> 2, ng = wid & 3;
    mainloop_32x32(acc, sb, mt, ng, lane);

    // epilogue: bias + relu + classifier partials over this thread's 8 cols
    const float* bp  = (const float*)(sm + OFF_BIAS);
    const float* wcs = (const float*)(sm + OFF_WC);
    float p[2][2][4];
#pragma unroll
    for (int at = 0; at < 2; at++)
#pragma unroll
        for (int hh = 0; hh < 2; hh++)
#pragma unroll
            for (int c = 0; c < 4; c++) p[at][hh][c] = 0.f;

#pragma unroll
    for (int at = 0; at < 2; at++)
#pragma unroll
        for (int j = 0; j < 4; j++) {
            const int col = ng * 32 + (j >> 1) * 16 + (j & 1) * 8 + (lane & 3) * 2;
            const float2 bb = *(const float2*)(bp + col);
            const float ha = fmaxf(acc[at][j][0] + bb.x, 0.f);
            const float hb = fmaxf(acc[at][j][1] + bb.y, 0.f);
            const float hc = fmaxf(acc[at][j][2] + bb.x, 0.f);
            const float hd = fmaxf(acc[at][j][3] + bb.y, 0.f);
#pragma unroll
            for (int c = 0; c < 4; c++) {
                const float2 w = *(const float2*)(wcs + c * 128 + col);
                p[at][0][c] = fmaf(ha, w.x, fmaf(hb, w.y, p[at][0][c]));
                p[at][1][c] = fmaf(hc, w.x, fmaf(hd, w.y, p[at][1][c]));
            }
        }
#pragma unroll
    for (int d = 1; d < 4; d <<= 1)
#pragma unroll
        for (int at = 0; at < 2; at++)
#pragma unroll
            for (int hh = 0; hh < 2; hh++)
#pragma unroll
                for (int c = 0; c < 4; c++)
                    p[at][hh][c] += __shfl_xor_sync(0xffffffffu, p[at][hh][c], d);

    float* cpart = (float*)(sm + OFF_CP);
    if ((lane & 3) == 0) {
#pragma unroll
        for (int at = 0; at < 2; at++) {
            const int rl = mt * 32 + at * 16 + (lane >> 2);
#pragma unroll
            for (int c = 0; c < 4; c++) {
                cpart[(ng * 64 + rl) * 4 + c]     = p[at][0][c];
                cpart[(ng * 64 + rl + 8) * 4 + c] = p[at][1][c];
            }
        }
    }
    __syncthreads();
    {
        const int rl = tid >> 2, c = tid & 3;
        const int r = R0 + rl;
        if (r < n) {
            const float* bcp = (const float*)(sm + OFF_BC);
            out[(size_t)r * 4 + c] =
                ((cpart[rl * 4 + c] + cpart[(64 + rl) * 4 + c]) +
                 (cpart[(128 + rl) * 4 + c] + cpart[(192 + rl) * 4 + c])) + bcp[c];
        }
    }
}

// ---------------------------------------------------------------------------
extern "C" void kernel_launch(void* const* d_in, const int* in_sizes, int n_in,
                              void* d_out, int out_size)
{
    const float* x  = (const float*)d_in[0];
    const int*   ei = (const int*)  d_in[1];
    const float* W0 = (const float*)d_in[2];
    const float* b0 = (const float*)d_in[3];
    const float* W1 = (const float*)d_in[4];
    const float* b1 = (const float*)d_in[5];
    const float* Wc = (const float*)d_in[6];
    const float* bc = (const float*)d_in[7];
    float* out = (float*)d_out;

    const int n       = in_sizes[0] / DIM;
    const int n_edges = in_sizes[1] / 2;

    void* hp;
    cudaGetSymbolAddress(&hp, g_h);

    cudaFuncSetAttribute(gemm0_mma, cudaFuncAttributeMaxDynamicSharedMemorySize, SMEM_BYTES);
    cudaFuncSetAttribute(gemm1_mma, cudaFuncAttributeMaxDynamicSharedMemorySize, SMEM_BYTES);

    prep_w<<<2, 256>>>(W0, W1);

    const int gblocks = (n + 63) / 64;
    gemm0_mma<<<gblocks, 256, SMEM_BYTES>>>(x, b0, (float*)hp, n);
    scatter_kernel<<<(n_edges + 7) / 8, 256>>>(ei, n_edges);
    gemm1_mma<<<gblocks, 256, SMEM_BYTES>>>(b1, Wc, bc, out, n);
}

// round 17
// speedup vs baseline: 1.0605x; 1.0605x over previous
#include <cuda_runtime.h>
#include <cuda_bf16.h>
#include <cstdint>

#define NODES_MAX 100000
#define DIM 128

typedef unsigned int u32;

// Scratch (allocation-free rule: __device__ globals)
__device__ float g_h[(size_t)NODES_MAX * DIM];     // relu(x@W0^T+b0)
__device__ float g_agg[(size_t)NODES_MAX * DIM];   // scatter-add accumulator
__device__ float g_deg[NODES_MAX];                 // degree accumulator
__device__ uint4 g_w0s[4096];                      // W0 split-bf16, swizzled tile layout (hi 2048, lo 2048)
__device__ uint4 g_w1s[4096];                      // W1 split-bf16, swizzled tile layout

// ---------------- smem layout (bytes) ----------------
#define OFF_BIAS 0            // 128 f32
#define OFF_WC   512          // 512 f32
#define OFF_BC   2560         // 4 f32
#define OFF_INVD 2576         // 64 f32
#define OFF_CP   4096         // 4KB classifier cross-warp partials
#define OFF_AH   8192         // 16KB (64x128 bf16)
#define OFF_AL   24576        // 16KB
#define OFF_BH   40960        // 32KB (128x128 bf16)
#define OFF_BL   73728        // 32KB (must be OFF_BH + 32768 for linear B copy)
#define SMEM_BYTES 106496

// ---------------- helpers ----------------
__device__ __forceinline__ u32 smem_u32(const void* p) {
    u32 a;
    asm("{ .reg .u64 t; cvta.to.shared.u64 t, %1; cvt.u32.u64 %0, t; }" : "=r"(a) : "l"(p));
    return a;
}

__device__ __forceinline__ void cp_async16(u32 smem, const void* gptr) {
    asm volatile("cp.async.cg.shared.global [%0], [%1], 16;" :: "r"(smem), "l"(gptr));
}

__device__ __forceinline__ void ldsm_x4(u32* r, u32 addr) {
    asm volatile("ldmatrix.sync.aligned.m8n8.x4.shared.b16 {%0,%1,%2,%3}, [%4];"
                 : "=r"(r[0]), "=r"(r[1]), "=r"(r[2]), "=r"(r[3]) : "r"(addr));
}

__device__ __forceinline__ void mma_bf16(float* d, const u32* a, u32 b0, u32 b1) {
    asm volatile(
        "mma.sync.aligned.m16n8k16.row.col.f32.bf16.bf16.f32 "
        "{%0,%1,%2,%3}, {%4,%5,%6,%7}, {%8,%9}, {%0,%1,%2,%3};"
        : "+f"(d[0]), "+f"(d[1]), "+f"(d[2]), "+f"(d[3])
        : "r"(a[0]), "r"(a[1]), "r"(a[2]), "r"(a[3]), "r"(b0), "r"(b1));
}

// byte offset of 16B chunk (row, c8) in a 256B-pitch tile, XOR-8 swizzle
__device__ __forceinline__ u32 tile_off(int row, int c8) {
    return (u32)(row * 256 + (((c8 >> 3) ^ (row & 7)) << 4));
}

// hi/lo bf16 split of 8 floats -> two 16B chunks
__device__ __forceinline__ void split8(const float* v, uint4& hi, uint4& lo) {
    u32 h[4], l[4];
#pragma unroll
    for (int j = 0; j < 4; j++) {
        float2 f = make_float2(v[2*j], v[2*j+1]);
        __nv_bfloat162 hb = __float22bfloat162_rn(f);
        float2 hf = __bfloat1622float2(hb);
        float2 r = make_float2(f.x - hf.x, f.y - hf.y);
        __nv_bfloat162 lb = __float22bfloat162_rn(r);
        h[j] = *(u32*)&hb;
        l[j] = *(u32*)&lb;
    }
    hi = make_uint4(h[0], h[1], h[2], h[3]);
    lo = make_uint4(l[0], l[1], l[2], l[3]);
}

__device__ __forceinline__ void split_store(char* smb, int hi_off, int lo_off,
                                            u32 sw, const float* v) {
    uint4 hi, lo;
    split8(v, hi, lo);
    *(uint4*)(smb + hi_off + sw) = hi;
    *(uint4*)(smb + lo_off + sw) = lo;
}

// ---------------------------------------------------------------------------
// Prep: split W0/W1 into bf16 hi/lo, stored in the EXACT swizzled tile layout
// so GEMM CTAs stage B with a pure linear 16B-chunk copy. blockIdx.x: 0=W0,1=W1
// ---------------------------------------------------------------------------
__global__ __launch_bounds__(256) void prep_w(const float* __restrict__ W0,
                                              const float* __restrict__ W1)
{
    const float* W = blockIdx.x ? W1 : W0;
    uint4* dst     = blockIdx.x ? g_w1s : g_w0s;
    const int tid = threadIdx.x;
#pragma unroll
    for (int s = 0; s < 8; s++) {
        const int chunk = tid + s * 256;          // 0..2047
        const int row = chunk >> 4, c8 = (chunk & 15) << 3;
        float w[8];
        float4 w0 = *(const float4*)(W + row * DIM + c8);
        float4 w1 = *(const float4*)(W + row * DIM + c8 + 4);
        w[0]=w0.x; w[1]=w0.y; w[2]=w0.z; w[3]=w0.w;
        w[4]=w1.x; w[5]=w1.y; w[6]=w1.z; w[7]=w1.w;
        uint4 hi, lo;
        split8(w, hi, lo);
        const u32 off = tile_off(row, c8) >> 4;
        dst[off]        = hi;
        dst[2048 + off] = lo;
    }
}

// stage B: pure async copy of the prepped 64KB (hi 32KB @ OFF_BH, lo follows)
__device__ __forceinline__ void stage_B_copy(u32 sb, const uint4* __restrict__ src, int tid) {
#pragma unroll
    for (int s = 0; s < 16; s++) {
        const int i = tid + s * 256;              // 0..4095
        cp_async16(sb + OFF_BH + i * 16, src + i);
    }
    asm volatile("cp.async.commit_group;" ::: "memory");
}

// mainloop: warp tile 32m x 32n. mt = m-half (0..1), ng = n-quarter (0..3).
__device__ __forceinline__ void mainloop_32x32(float acc[2][4][4], u32 sb,
                                               int mt, int ng, int lane) {
    const int l7     = lane & 7;
    const int a_sel  = lane >> 4;
    const int b_rowl = l7 + ((lane >> 4) << 3);
    const int b_sel  = (lane >> 3) & 1;
    const int arow0  = mt * 32 + (lane & 15);

    u32 aH[2][4], aL[2][4], bH[2][4], bL[2][4];
#pragma unroll
    for (int kk = 0; kk < 8; kk++) {
        const u32 ao = (u32)(((2 * kk + a_sel) ^ l7) << 4);
        const u32 bo = (u32)(((2 * kk + b_sel) ^ l7) << 4);
#pragma unroll
        for (int at = 0; at < 2; at++) {
            const u32 ar = (u32)((arow0 + at * 16) * 256);
            ldsm_x4(aH[at], sb + OFF_AH + ar + ao);
            ldsm_x4(aL[at], sb + OFF_AL + ar + ao);
        }
#pragma unroll
        for (int g = 0; g < 2; g++) {
            const u32 br = (u32)((ng * 32 + g * 16 + b_rowl) * 256);
            ldsm_x4(bH[g], sb + OFF_BH + br + bo);
            ldsm_x4(bL[g], sb + OFF_BL + br + bo);
        }
#pragma unroll
        for (int at = 0; at < 2; at++)
#pragma unroll
            for (int g = 0; g < 2; g++) {
                mma_bf16(acc[at][2*g],   aH[at], bH[g][0], bH[g][1]);
                mma_bf16(acc[at][2*g+1], aH[at], bH[g][2], bH[g][3]);
            }
#pragma unroll
        for (int at = 0; at < 2; at++)
#pragma unroll
            for (int g = 0; g < 2; g++) {
                mma_bf16(acc[at][2*g],   aH[at], bL[g][0], bL[g][1]);
                mma_bf16(acc[at][2*g+1], aH[at], bL[g][2], bL[g][3]);
            }
#pragma unroll
        for (int at = 0; at < 2; at++)
#pragma unroll
            for (int g = 0; g < 2; g++) {
                mma_bf16(acc[at][2*g],   aL[at], bH[g][0], bH[g][1]);
                mma_bf16(acc[at][2*g+1], aL[at], bH[g][2], bH[g][3]);
            }
    }
}

// ---------------------------------------------------------------------------
// GEMM0: h = relu(x @ W0^T + b0). CTA 64x128, 256 threads, warps 2m x 4n.
// ---------------------------------------------------------------------------
__global__ __launch_bounds__(256, 2) void gemm0_mma(
    const float* __restrict__ A,
    const float* __restrict__ bias, float* __restrict__ C, int n)
{
    extern __shared__ char sm[];
    const u32 sb = smem_u32(sm);
    const int tid = threadIdx.x, wid = tid >> 5, lane = tid & 31;
    const int R0 = blockIdx.x * 64;

    stage_B_copy(sb, g_w0s, tid);   // async B while we stage A

    if (tid < 128) ((float*)(sm + OFF_BIAS))[tid] = bias[tid];

    // stage A (64x128, split bf16)
#pragma unroll
    for (int s = 0; s < 4; s++) {
        const int chunk = tid + s * 256;
        const int row = chunk >> 4, c8 = (chunk & 15) << 3;
        const u32 sw = tile_off(row, c8);
        float v[8];
        const int gr = R0 + row;
        if (gr < n) {
            float4 a0 = *(const float4*)(A + (size_t)gr * DIM + c8);
            float4 a1 = *(const float4*)(A + (size_t)gr * DIM + c8 + 4);
            v[0]=a0.x; v[1]=a0.y; v[2]=a0.z; v[3]=a0.w;
            v[4]=a1.x; v[5]=a1.y; v[6]=a1.z; v[7]=a1.w;
        } else {
#pragma unroll
            for (int j = 0; j < 8; j++) v[j] = 0.f;
        }
        split_store(sm, OFF_AH, OFF_AL, sw, v);
    }
    asm volatile("cp.async.wait_group 0;" ::: "memory");
    __syncthreads();

    float acc[2][4][4];
#pragma unroll
    for (int at = 0; at < 2; at++)
#pragma unroll
        for (int j = 0; j < 4; j++)
#pragma unroll
            for (int q = 0; q < 4; q++) acc[at][j][q] = 0.f;

    const int mt = wid >> 2, ng = wid & 3;
    mainloop_32x32(acc, sb, mt, ng, lane);

    // epilogue: bias + relu -> C
    const float* bp = (const float*)(sm + OFF_BIAS);
#pragma unroll
    for (int at = 0; at < 2; at++) {
        const int r0 = R0 + mt * 32 + at * 16 + (lane >> 2), r1 = r0 + 8;
#pragma unroll
        for (int j = 0; j < 4; j++) {
            const int col = ng * 32 + (j >> 1) * 16 + (j & 1) * 8 + (lane & 3) * 2;
            const float2 bb = *(const float2*)(bp + col);
            if (r0 < n) {
                float2 o = make_float2(fmaxf(acc[at][j][0] + bb.x, 0.f),
                                       fmaxf(acc[at][j][1] + bb.y, 0.f));
                *(float2*)(C + (size_t)r0 * DIM + col) = o;
            }
            if (r1 < n) {
                float2 o = make_float2(fmaxf(acc[at][j][2] + bb.x, 0.f),
                                       fmaxf(acc[at][j][3] + bb.y, 0.f));
                *(float2*)(C + (size_t)r1 * DIM + col) = o;
            }
        }
    }
}

// ---------------------------------------------------------------------------
// Scatter: one warp per edge. agg[row] += h[col] (vectorized RED), deg[row]+=1
// ---------------------------------------------------------------------------
__global__ __launch_bounds__(256) void scatter_kernel(
    const int* __restrict__ ei, int n_edges)
{
    int e    = blockIdx.x * 8 + (threadIdx.x >> 5);
    int lane = threadIdx.x & 31;
    if (e >= n_edges) return;
    int r = ei[e];
    int c = ei[n_edges + e];

    const float4 v = *(const float4*)(g_h + (size_t)c * DIM + lane * 4);
    float* dst = g_agg + (size_t)r * DIM + lane * 4;
    asm volatile("red.global.add.v4.f32 [%0], {%1,%2,%3,%4};"
                 :: "l"(dst), "f"(v.x), "f"(v.y), "f"(v.z), "f"(v.w)
                 : "memory");
    if (lane == 0)
        asm volatile("red.global.add.f32 [%0], %1;"
                     :: "l"(g_deg + r), "f"(1.0f) : "memory");
}

// ---------------------------------------------------------------------------
// GEMM1 + classifier: a = h + agg/max(deg,1); h2 = relu(a@W1^T+b1);
// out = h2@Wc^T+bc. cp.async B staging; read-only agg/deg (memset zeroes them).
// ---------------------------------------------------------------------------
__global__ __launch_bounds__(256, 2) void gemm1_mma(
    const float* __restrict__ b1,
    const float* __restrict__ Wc, const float* __restrict__ bc,
    float* __restrict__ out, int n)
{
    extern __shared__ char sm[];
    const u32 sb = smem_u32(sm);
    const int tid = threadIdx.x, wid = tid >> 5, lane = tid & 31;
    const int R0 = blockIdx.x * 64;

    stage_B_copy(sb, g_w1s, tid);   // async B while we stage A

    if (tid < 128) ((float*)(sm + OFF_BIAS))[tid] = b1[tid];
    ((float*)(sm + OFF_WC))[tid]       = Wc[tid];
    ((float*)(sm + OFF_WC))[tid + 256] = Wc[tid + 256];
    if (tid < 4) ((float*)(sm + OFF_BC))[tid] = bc[tid];
    if (tid < 64) {
        const int r = R0 + tid;
        ((float*)(sm + OFF_INVD))[tid] =
            (r < n) ? (1.0f / fmaxf(g_deg[r], 1.0f)) : 0.f;
    }
    __syncthreads();   // invd visible before A staging reads it
    const float* invd_s = (const float*)(sm + OFF_INVD);

    // stage A = h + agg*invd (64x128, split bf16)
#pragma unroll
    for (int s = 0; s < 4; s++) {
        const int chunk = tid + s * 256;
        const int row = chunk >> 4, c8 = (chunk & 15) << 3;
        const u32 sw = tile_off(row, c8);
        float v[8];
        const int gr = R0 + row;
        if (gr < n) {
            const float id = invd_s[row];
            float4 h0 = *(const float4*)(g_h   + (size_t)gr * DIM + c8);
            float4 h1 = *(const float4*)(g_h   + (size_t)gr * DIM + c8 + 4);
            float4 g0 = *(const float4*)(g_agg + (size_t)gr * DIM + c8);
            float4 g1 = *(const float4*)(g_agg + (size_t)gr * DIM + c8 + 4);
            v[0]=fmaf(g0.x,id,h0.x); v[1]=fmaf(g0.y,id,h0.y);
            v[2]=fmaf(g0.z,id,h0.z); v[3]=fmaf(g0.w,id,h0.w);
            v[4]=fmaf(g1.x,id,h1.x); v[5]=fmaf(g1.y,id,h1.y);
            v[6]=fmaf(g1.z,id,h1.z); v[7]=fmaf(g1.w,id,h1.w);
        } else {
#pragma unroll
            for (int j = 0; j < 8; j++) v[j] = 0.f;
        }
        split_store(sm, OFF_AH, OFF_AL, sw, v);
    }
    asm volatile("cp.async.wait_group 0;" ::: "memory");
    __syncthreads();

    float acc[2][4][4];
#pragma unroll
    for (int at = 0; at < 2; at++)
#pragma unroll
        for (int j = 0; j < 4; j++)
#pragma unroll
            for (int q = 0; q < 4; q++) acc[at][j][q] = 0.f;

    const int mt = wid >> 2, ng = wid & 3;
    mainloop_32x32(acc, sb, mt, ng, lane);

    // epilogue: bias + relu + classifier partials over this thread's 8 cols
    const float* bp  = (const float*)(sm + OFF_BIAS);
    const float* wcs = (const float*)(sm + OFF_WC);
    float p[2][2][4];
#pragma unroll
    for (int at = 0; at < 2; at++)
#pragma unroll
        for (int hh = 0; hh < 2; hh++)
#pragma unroll
            for (int c = 0; c < 4; c++) p[at][hh][c] = 0.f;

#pragma unroll
    for (int at = 0; at < 2; at++)
#pragma unroll
        for (int j = 0; j < 4; j++) {
            const int col = ng * 32 + (j >> 1) * 16 + (j & 1) * 8 + (lane & 3) * 2;
            const float2 bb = *(const float2*)(bp + col);
            const float ha = fmaxf(acc[at][j][0] + bb.x, 0.f);
            const float hb = fmaxf(acc[at][j][1] + bb.y, 0.f);
            const float hc = fmaxf(acc[at][j][2] + bb.x, 0.f);
            const float hd = fmaxf(acc[at][j][3] + bb.y, 0.f);
#pragma unroll
            for (int c = 0; c < 4; c++) {
                const float2 w = *(const float2*)(wcs + c * 128 + col);
                p[at][0][c] = fmaf(ha, w.x, fmaf(hb, w.y, p[at][0][c]));
                p[at][1][c] = fmaf(hc, w.x, fmaf(hd, w.y, p[at][1][c]));
            }
        }
#pragma unroll
    for (int d = 1; d < 4; d <<= 1)
#pragma unroll
        for (int at = 0; at < 2; at++)
#pragma unroll
            for (int hh = 0; hh < 2; hh++)
#pragma unroll
                for (int c = 0; c < 4; c++)
                    p[at][hh][c] += __shfl_xor_sync(0xffffffffu, p[at][hh][c], d);

    float* cpart = (float*)(sm + OFF_CP);
    if ((lane & 3) == 0) {
#pragma unroll
        for (int at = 0; at < 2; at++) {
            const int rl = mt * 32 + at * 16 + (lane >> 2);
#pragma unroll
            for (int c = 0; c < 4; c++) {
                cpart[(ng * 64 + rl) * 4 + c]     = p[at][0][c];
                cpart[(ng * 64 + rl + 8) * 4 + c] = p[at][1][c];
            }
        }
    }
    __syncthreads();
    {
        const int rl = tid >> 2, c = tid & 3;
        const int r = R0 + rl;
        if (r < n) {
            const float* bcp = (const float*)(sm + OFF_BC);
            out[(size_t)r * 4 + c] =
                ((cpart[rl * 4 + c] + cpart[(64 + rl) * 4 + c]) +
                 (cpart[(128 + rl) * 4 + c] + cpart[(192 + rl) * 4 + c])) + bcp[c];
        }
    }
}

// ---------------------------------------------------------------------------
extern "C" void kernel_launch(void* const* d_in, const int* in_sizes, int n_in,
                              void* d_out, int out_size)
{
    const float* x  = (const float*)d_in[0];
    const int*   ei = (const int*)  d_in[1];
    const float* W0 = (const float*)d_in[2];
    const float* b0 = (const float*)d_in[3];
    const float* W1 = (const float*)d_in[4];
    const float* b1 = (const float*)d_in[5];
    const float* Wc = (const float*)d_in[6];
    const float* bc = (const float*)d_in[7];
    float* out = (float*)d_out;

    const int n       = in_sizes[0] / DIM;
    const int n_edges = in_sizes[1] / 2;

    void *aggp, *degp, *hp;
    cudaGetSymbolAddress(&aggp, g_agg);
    cudaGetSymbolAddress(&degp, g_deg);
    cudaGetSymbolAddress(&hp,   g_h);

    cudaFuncSetAttribute(gemm0_mma, cudaFuncAttributeMaxDynamicSharedMemorySize, SMEM_BYTES);
    cudaFuncSetAttribute(gemm1_mma, cudaFuncAttributeMaxDynamicSharedMemorySize, SMEM_BYTES);

    prep_w<<<2, 256>>>(W0, W1);
    cudaMemsetAsync(aggp, 0, (size_t)n * DIM * sizeof(float));
    cudaMemsetAsync(degp, 0, (size_t)n * sizeof(float));

    const int gblocks = (n + 63) / 64;
    gemm0_mma<<<gblocks, 256, SMEM_BYTES>>>(x, b0, (float*)hp, n);
    scatter_kernel<<<(n_edges + 7) / 8, 256>>>(ei, n_edges);
    gemm1_mma<<<gblocks, 256, SMEM_BYTES>>>(b1, Wc, bc, out, n);
}